// round 1
// baseline (speedup 1.0000x reference)
#include <cuda_runtime.h>
#include <math.h>

// Problem constants
#define Bb 2
#define Hh 8
#define Ss 2048
#define Dd 512
#define Mrows (Bb * Ss)          // 4096
#define CONCAT_K (Hh * Dd)       // 4096

// Scratch (device globals: allocation inside kernel_launch is forbidden)
__device__ float gQ[(size_t)Hh * Mrows * Dd];        // 64 MB  [h][b*S+s][e]
__device__ float gK[(size_t)Hh * Mrows * Dd];        // 64 MB
__device__ float gV[(size_t)Hh * Mrows * Dd];        // 64 MB
__device__ float gS[(size_t)Bb * Hh * Ss * Ss];      // 256 MB [b*H+h][q][k]
__device__ float gO[(size_t)Hh * Mrows * Dd];        // 64 MB  [h][b*S+s][e]
__device__ float gC[(size_t)Mrows * CONCAT_K];       // 64 MB  [m][h*D+e]

// ----------------------------------------------------------------------------
// Generic fp32 SGEMM: C = alpha * A @ B(^T) (+ bias[col]) (+ resid)
// Block tile 128x128x8, thread tile 8x8 (split 4+4 at +64 for conflict-free
// LDS.128), 256 threads. All problem dims divide the tiles -> no bounds checks.
//
// MODE selects per-blockIdx.z batch offset arithmetic:
//   0: QKV proj   z=h      : B += z*D*D, C += z*Mrows*D, bias += z*D
//   1: Q@K^T      z=b*8+h  : A,B += (h*Mrows + b*S)*D,  C += z*S*S
//   2: P@V        z=b*8+h  : A += z*S*S,  B,C += (h*Mrows + b*S)*D
//   3: out proj   z=0      : no offsets, resid active
// ----------------------------------------------------------------------------
template <int MODE, bool TRANSB>
__global__ __launch_bounds__(256, 2)
void sgemm_kernel(const float* __restrict__ A0, const float* __restrict__ B0,
                  float* __restrict__ C0, const float* __restrict__ bias0,
                  const float* __restrict__ resid0,
                  int M, int N, int K, float alpha)
{
    __shared__ float As[8][136];   // padded: k-stride 136 floats (16B aligned, bank-skewed)
    __shared__ float Bs[8][136];

    const float* A = A0;
    const float* Bm = B0;
    float* C = C0;
    const float* bias = bias0;
    {
        const int z = blockIdx.z;
        if (MODE == 0) {
            Bm += (size_t)z * Dd * Dd;
            C  += (size_t)z * Mrows * Dd;
            if (bias) bias += (size_t)z * Dd;
        } else if (MODE == 1) {
            const int h = z & 7, b = z >> 3;
            const size_t off = ((size_t)h * Mrows + (size_t)b * Ss) * Dd;
            A += off; Bm += off;
            C += (size_t)z * Ss * Ss;
        } else if (MODE == 2) {
            const int h = z & 7, b = z >> 3;
            A += (size_t)z * Ss * Ss;
            const size_t off = ((size_t)h * Mrows + (size_t)b * Ss) * Dd;
            Bm += off; C += off;
        }
    }

    const int tid = threadIdx.x;
    const int tx = tid & 15;       // 16 cols of threads
    const int ty = tid >> 4;       // 16 rows of threads

    // A tile load: 128 rows x 8 k, one float4 per thread along k
    const int a_r = tid >> 1;
    const int a_c = (tid & 1) * 4;

    const float* Aptr = A + (size_t)(blockIdx.y * 128 + a_r) * K + a_c;
    const float* Bptr;
    if (TRANSB) {
        // B is [N, K] row-major; tile: 128 n-rows x 8 k
        Bptr = Bm + (size_t)(blockIdx.x * 128 + a_r) * K + a_c;
    } else {
        // B is [K, N] row-major; tile: 8 k-rows x 128 n
        Bptr = Bm + (size_t)(tid >> 5) * N + blockIdx.x * 128 + (tid & 31) * 4;
    }

    float acc[8][8];
#pragma unroll
    for (int i = 0; i < 8; i++)
#pragma unroll
        for (int j = 0; j < 8; j++) acc[i][j] = 0.0f;

    for (int k0 = 0; k0 < K; k0 += 8) {
        const float4 av = *(const float4*)Aptr;
        As[a_c + 0][a_r] = av.x; As[a_c + 1][a_r] = av.y;
        As[a_c + 2][a_r] = av.z; As[a_c + 3][a_r] = av.w;
        const float4 bv = *(const float4*)Bptr;
        if (TRANSB) {
            Bs[a_c + 0][a_r] = bv.x; Bs[a_c + 1][a_r] = bv.y;
            Bs[a_c + 2][a_r] = bv.z; Bs[a_c + 3][a_r] = bv.w;
        } else {
            *(float4*)&Bs[tid >> 5][(tid & 31) * 4] = bv;
        }
        __syncthreads();

#pragma unroll
        for (int kk = 0; kk < 8; kk++) {
            float a[8], b[8];
            *(float4*)&a[0] = *(const float4*)&As[kk][ty * 4];
            *(float4*)&a[4] = *(const float4*)&As[kk][64 + ty * 4];
            *(float4*)&b[0] = *(const float4*)&Bs[kk][tx * 4];
            *(float4*)&b[4] = *(const float4*)&Bs[kk][64 + tx * 4];
#pragma unroll
            for (int i = 0; i < 8; i++)
#pragma unroll
                for (int j = 0; j < 8; j++)
                    acc[i][j] = fmaf(a[i], b[j], acc[i][j]);
        }
        __syncthreads();

        Aptr += 8;
        if (TRANSB) Bptr += 8; else Bptr += (size_t)8 * N;
    }

    // Epilogue: rows {ty*4+i, 64+ty*4+i}, cols {tx*4.., 64+tx*4..}
#pragma unroll
    for (int i = 0; i < 8; i++) {
        const int lr = (i < 4) ? (ty * 4 + i) : (64 + ty * 4 + (i - 4));
        const int r = blockIdx.y * 128 + lr;
#pragma unroll
        for (int jj = 0; jj < 2; jj++) {
            const int c0 = blockIdx.x * 128 + jj * 64 + tx * 4;
            float4 v;
            v.x = acc[i][jj * 4 + 0] * alpha;
            v.y = acc[i][jj * 4 + 1] * alpha;
            v.z = acc[i][jj * 4 + 2] * alpha;
            v.w = acc[i][jj * 4 + 3] * alpha;
            if (bias0) {
                v.x += bias[c0 + 0]; v.y += bias[c0 + 1];
                v.z += bias[c0 + 2]; v.w += bias[c0 + 3];
            }
            if (resid0) {
                const float4 rv = *(const float4*)&resid0[(size_t)r * N + c0];
                v.x += rv.x; v.y += rv.y; v.z += rv.z; v.w += rv.w;
            }
            *(float4*)&C[(size_t)r * N + c0] = v;
        }
    }
}

// ----------------------------------------------------------------------------
// Row softmax: one block per row of 2048, 256 threads x 8 elements
// ----------------------------------------------------------------------------
__global__ __launch_bounds__(256)
void softmax_kernel(float* __restrict__ S)
{
    __shared__ float red[256];
    float* p = S + (size_t)blockIdx.x * Ss;
    const int t = threadIdx.x;

    float4 v0 = ((const float4*)p)[t];
    float4 v1 = ((const float4*)p)[t + 256];

    float m = fmaxf(fmaxf(fmaxf(v0.x, v0.y), fmaxf(v0.z, v0.w)),
                    fmaxf(fmaxf(v1.x, v1.y), fmaxf(v1.z, v1.w)));
    red[t] = m;
    __syncthreads();
    for (int s = 128; s > 0; s >>= 1) {
        if (t < s) red[t] = fmaxf(red[t], red[t + s]);
        __syncthreads();
    }
    m = red[0];
    __syncthreads();

    v0.x = expf(v0.x - m); v0.y = expf(v0.y - m);
    v0.z = expf(v0.z - m); v0.w = expf(v0.w - m);
    v1.x = expf(v1.x - m); v1.y = expf(v1.y - m);
    v1.z = expf(v1.z - m); v1.w = expf(v1.w - m);

    red[t] = v0.x + v0.y + v0.z + v0.w + v1.x + v1.y + v1.z + v1.w;
    __syncthreads();
    for (int s = 128; s > 0; s >>= 1) {
        if (t < s) red[t] += red[t + s];
        __syncthreads();
    }
    const float inv = 1.0f / red[0];

    v0.x *= inv; v0.y *= inv; v0.z *= inv; v0.w *= inv;
    v1.x *= inv; v1.y *= inv; v1.z *= inv; v1.w *= inv;
    ((float4*)p)[t] = v0;
    ((float4*)p)[t + 256] = v1;
}

// ----------------------------------------------------------------------------
// Head concat: gC[m][h*512+e] = gO[h][m][e]   (float4 granularity)
// ----------------------------------------------------------------------------
__global__ __launch_bounds__(256)
void repack_kernel(const float* __restrict__ O, float* __restrict__ Cc)
{
    const size_t i = (size_t)blockIdx.x * blockDim.x + threadIdx.x;  // float4 idx
    const int col4 = (int)(i & 1023);        // 4096/4 per row
    const size_t m = i >> 10;
    const int h = col4 >> 7;                 // /128 float4s per head slice
    const int e4 = col4 & 127;
    ((float4*)Cc)[i] = ((const float4*)O)[((size_t)h * Mrows + m) * (Dd / 4) + e4];
}

// ----------------------------------------------------------------------------
extern "C" void kernel_launch(void* const* d_in, const int* in_sizes, int n_in,
                              void* d_out, int out_size)
{
    const float* x  = (const float*)d_in[0];
    const float* Wq = (const float*)d_in[1];
    const float* Wk = (const float*)d_in[2];
    const float* Wv = (const float*)d_in[3];
    const float* bq = (const float*)d_in[4];
    const float* bk = (const float*)d_in[5];
    const float* bv = (const float*)d_in[6];
    const float* Wo = (const float*)d_in[7];
    const float* bo = (const float*)d_in[8];
    float* out = (float*)d_out;

    float *pQ, *pK, *pV, *pS, *pO, *pC;
    cudaGetSymbolAddress((void**)&pQ, gQ);
    cudaGetSymbolAddress((void**)&pK, gK);
    cudaGetSymbolAddress((void**)&pV, gV);
    cudaGetSymbolAddress((void**)&pS, gS);
    cudaGetSymbolAddress((void**)&pO, gO);
    cudaGetSymbolAddress((void**)&pC, gC);

    const float scale = 0.044194173824159216f;  // 1/sqrt(512)
    const dim3 blk(256);

    // QKV projections: per head, [4096,512] = x[4096,512] @ W[h][512,512] + b[h]
    sgemm_kernel<0, false><<<dim3(4, 32, Hh), blk>>>(x, Wq, pQ, bq, nullptr, Mrows, Dd, Dd, 1.0f);
    sgemm_kernel<0, false><<<dim3(4, 32, Hh), blk>>>(x, Wk, pK, bk, nullptr, Mrows, Dd, Dd, 1.0f);
    sgemm_kernel<0, false><<<dim3(4, 32, Hh), blk>>>(x, Wv, pV, bv, nullptr, Mrows, Dd, Dd, 1.0f);

    // scores = scale * Q @ K^T  per (b,h): [2048,2048]
    sgemm_kernel<1, true><<<dim3(16, 16, Bb * Hh), blk>>>(pQ, pK, pS, nullptr, nullptr, Ss, Ss, Dd, scale);

    // softmax over last axis
    softmax_kernel<<<Bb * Hh * Ss, 256>>>(pS);

    // O = P @ V  per (b,h): [2048,512]
    sgemm_kernel<2, false><<<dim3(4, 16, Bb * Hh), blk>>>(pS, pV, pO, nullptr, nullptr, Ss, Dd, Ss, 1.0f);

    // concat heads
    repack_kernel<<<(Mrows * CONCAT_K / 4) / 256, 256>>>(pO, pC);

    // out = concat @ Wo + bo + x
    sgemm_kernel<3, false><<<dim3(4, 32, 1), blk>>>(pC, Wo, out, bo, x, Mrows, Dd, CONCAT_K, 1.0f);
}

// round 2
// speedup vs baseline: 2.2983x; 2.2983x over previous
#include <cuda_runtime.h>
#include <math.h>
#include <stdint.h>

// Problem constants
#define Bb 2
#define Hh 8
#define Ss 2048
#define Dd 512
#define Mrows (Bb * Ss)          // 4096
#define CONCAT_K (Hh * Dd)       // 4096

// Scratch (device globals: allocation inside kernel_launch is forbidden)
__device__ float gQ[(size_t)Hh * Mrows * Dd];        // 64 MB  [h][b*S+s][e]
__device__ float gK[(size_t)Hh * Mrows * Dd];        // 64 MB
__device__ float gV[(size_t)Hh * Mrows * Dd];        // 64 MB
__device__ float gS[(size_t)Bb * Hh * Ss * Ss];      // 256 MB [b*H+h][q][k]
__device__ float gC[(size_t)Mrows * CONCAT_K];       // 64 MB  [m][h*D+e]  (PV writes here directly)

// ----------------------------------------------------------------------------
// TF32 tensor-core GEMM: C = alpha * A @ B(^T) (+ bias[col]) (+ resid)
// Block tile 128x128x16, 256 threads = 8 warps (2x4), warp tile 64x32.
// mma.sync.aligned.m16n8k8 tf32. All dims divide tiles exactly.
//
// MODE:
//   0: QKV proj   z=h      : B += z*D*D, C += z*Mrows*D, bias += z*D       ldc=512
//   1: Q@K^T      z=b*8+h  : A,B += (h*Mrows + b*S)*D,  C += z*S*S         ldc=2048
//   2: P@V        z=b*8+h  : A += z*S*S, B += (h*Mrows+b*S)*D,
//                            C += b*S*4096 + h*512                         ldc=4096
//   3: out proj   z=0      : resid active                                  ldc=512
// ----------------------------------------------------------------------------

__device__ __forceinline__ uint32_t f2tf(float x) {
    uint32_t u;
    asm("cvt.rna.tf32.f32 %0, %1;" : "=r"(u) : "f"(x));
    return u;
}

__device__ __forceinline__ void mma_tf32(float* c, const uint32_t* a, const uint32_t* b) {
    asm volatile(
        "mma.sync.aligned.m16n8k8.row.col.f32.tf32.tf32.f32 "
        "{%0,%1,%2,%3},{%4,%5,%6,%7},{%8,%9},{%0,%1,%2,%3};\n"
        : "+f"(c[0]), "+f"(c[1]), "+f"(c[2]), "+f"(c[3])
        : "r"(a[0]), "r"(a[1]), "r"(a[2]), "r"(a[3]), "r"(b[0]), "r"(b[1]));
}

#define AS_STRIDE 20    // conflict-free for a-frag reads (20*g mod 32 all distinct), 80B rows (16B aligned)
#define BS_STRIDE 140   // conflict-free for b-frag reads (12*tig+g mod 32 all distinct), 560B rows

template <int MODE, bool TRANSB>
__global__ __launch_bounds__(256, 2)
void mma_gemm(const float* __restrict__ A0, const float* __restrict__ B0,
              float* __restrict__ C0, const float* __restrict__ bias0,
              const float* __restrict__ resid0,
              int M, int N, int K, int ldc, float alpha)
{
    __shared__ uint32_t As[128][AS_STRIDE];  // [m][k], k=0..15
    __shared__ uint32_t Bs[16][BS_STRIDE];   // [k][n], n=0..127

    const float* A = A0;
    const float* Bm = B0;
    float* C = C0;
    const float* bias = bias0;
    {
        const int z = blockIdx.z;
        if (MODE == 0) {
            Bm += (size_t)z * Dd * Dd;
            C  += (size_t)z * Mrows * Dd;
            if (bias) bias += (size_t)z * Dd;
        } else if (MODE == 1) {
            const int h = z & 7, b = z >> 3;
            const size_t off = ((size_t)h * Mrows + (size_t)b * Ss) * Dd;
            A += off; Bm += off;
            C += (size_t)z * Ss * Ss;
        } else if (MODE == 2) {
            const int h = z & 7, b = z >> 3;
            A += (size_t)z * Ss * Ss;
            Bm += ((size_t)h * Mrows + (size_t)b * Ss) * Dd;
            C += (size_t)b * Ss * CONCAT_K + (size_t)h * Dd;
        }
    }

    const int tid = threadIdx.x;
    const int wid = tid >> 5;
    const int lane = tid & 31;
    const int g = lane >> 2;       // groupID 0..7
    const int tig = lane & 3;      // thread-in-group 0..3
    const int warp_m = wid >> 2;   // 0..1  (64-row slabs)
    const int warp_n = wid & 3;    // 0..3  (32-col slabs)

    const int bx = blockIdx.x, by = blockIdx.y;

    float acc[4][4][4];
#pragma unroll
    for (int mi = 0; mi < 4; mi++)
#pragma unroll
        for (int ni = 0; ni < 4; ni++)
#pragma unroll
            for (int r = 0; r < 4; r++) acc[mi][ni][r] = 0.0f;

    for (int k0 = 0; k0 < K; k0 += 16) {
        // ---- load A tile: 128 rows x 16 k (2 float4 per thread) ----
#pragma unroll
        for (int t = 0; t < 2; t++) {
            const int i = tid + t * 256;
            const int row = i >> 2, k4 = i & 3;
            const float4 v = *(const float4*)(A + (size_t)(by * 128 + row) * K + k0 + k4 * 4);
            uint4 u;
            u.x = f2tf(v.x); u.y = f2tf(v.y); u.z = f2tf(v.z); u.w = f2tf(v.w);
            *(uint4*)&As[row][k4 * 4] = u;
        }
        // ---- load B tile ----
        if (TRANSB) {
            // B is [N,K] row-major: read 128 n-rows x 16 k, transpose into Bs[k][n]
#pragma unroll
            for (int t = 0; t < 2; t++) {
                const int i = tid + t * 256;
                const int nr = i >> 2, k4 = i & 3;
                const float4 v = *(const float4*)(Bm + (size_t)(bx * 128 + nr) * K + k0 + k4 * 4);
                Bs[k4 * 4 + 0][nr] = f2tf(v.x);
                Bs[k4 * 4 + 1][nr] = f2tf(v.y);
                Bs[k4 * 4 + 2][nr] = f2tf(v.z);
                Bs[k4 * 4 + 3][nr] = f2tf(v.w);
            }
        } else {
            // B is [K,N] row-major: read 16 k-rows x 128 n
#pragma unroll
            for (int t = 0; t < 2; t++) {
                const int i = tid + t * 256;
                const int kr = i >> 5, n4 = i & 31;
                const float4 v = *(const float4*)(Bm + (size_t)(k0 + kr) * N + bx * 128 + n4 * 4);
                uint4 u;
                u.x = f2tf(v.x); u.y = f2tf(v.y); u.z = f2tf(v.z); u.w = f2tf(v.w);
                *(uint4*)&Bs[kr][n4 * 4] = u;
            }
        }
        __syncthreads();

        // ---- 2 k-steps of 8 ----
#pragma unroll
        for (int ks = 0; ks < 2; ks++) {
            const int k8 = ks * 8;
            uint32_t a[4][4], b[4][2];
#pragma unroll
            for (int mi = 0; mi < 4; mi++) {
                const int r0 = warp_m * 64 + mi * 16 + g;
                a[mi][0] = As[r0][k8 + tig];
                a[mi][1] = As[r0 + 8][k8 + tig];
                a[mi][2] = As[r0][k8 + tig + 4];
                a[mi][3] = As[r0 + 8][k8 + tig + 4];
            }
#pragma unroll
            for (int ni = 0; ni < 4; ni++) {
                const int c0 = warp_n * 32 + ni * 8 + g;
                b[ni][0] = Bs[k8 + tig][c0];
                b[ni][1] = Bs[k8 + tig + 4][c0];
            }
#pragma unroll
            for (int mi = 0; mi < 4; mi++)
#pragma unroll
                for (int ni = 0; ni < 4; ni++)
                    mma_tf32(acc[mi][ni], a[mi], b[ni]);
        }
        __syncthreads();
    }

    // ---- epilogue ----
#pragma unroll
    for (int mi = 0; mi < 4; mi++) {
        const int row0 = by * 128 + warp_m * 64 + mi * 16 + g;
#pragma unroll
        for (int ni = 0; ni < 4; ni++) {
            const int col = bx * 128 + warp_n * 32 + ni * 8 + 2 * tig;
            float2 v0, v1;
            v0.x = acc[mi][ni][0] * alpha; v0.y = acc[mi][ni][1] * alpha;
            v1.x = acc[mi][ni][2] * alpha; v1.y = acc[mi][ni][3] * alpha;
            if (bias0) {
                const float b0 = bias[col], b1 = bias[col + 1];
                v0.x += b0; v0.y += b1;
                v1.x += b0; v1.y += b1;
            }
            if (resid0) {
                const float2 r0 = *(const float2*)&resid0[(size_t)row0 * N + col];
                const float2 r1 = *(const float2*)&resid0[(size_t)(row0 + 8) * N + col];
                v0.x += r0.x; v0.y += r0.y;
                v1.x += r1.x; v1.y += r1.y;
            }
            *(float2*)&C[(size_t)row0 * ldc + col] = v0;
            *(float2*)&C[(size_t)(row0 + 8) * ldc + col] = v1;
        }
    }
}

// ----------------------------------------------------------------------------
// Row softmax: one block per row of 2048, 256 threads x 8 elements
// ----------------------------------------------------------------------------
__global__ __launch_bounds__(256)
void softmax_kernel(float* __restrict__ S)
{
    __shared__ float red[256];
    float* p = S + (size_t)blockIdx.x * Ss;
    const int t = threadIdx.x;

    float4 v0 = ((const float4*)p)[t];
    float4 v1 = ((const float4*)p)[t + 256];

    float m = fmaxf(fmaxf(fmaxf(v0.x, v0.y), fmaxf(v0.z, v0.w)),
                    fmaxf(fmaxf(v1.x, v1.y), fmaxf(v1.z, v1.w)));
    red[t] = m;
    __syncthreads();
    for (int s = 128; s > 0; s >>= 1) {
        if (t < s) red[t] = fmaxf(red[t], red[t + s]);
        __syncthreads();
    }
    m = red[0];
    __syncthreads();

    v0.x = expf(v0.x - m); v0.y = expf(v0.y - m);
    v0.z = expf(v0.z - m); v0.w = expf(v0.w - m);
    v1.x = expf(v1.x - m); v1.y = expf(v1.y - m);
    v1.z = expf(v1.z - m); v1.w = expf(v1.w - m);

    red[t] = v0.x + v0.y + v0.z + v0.w + v1.x + v1.y + v1.z + v1.w;
    __syncthreads();
    for (int s = 128; s > 0; s >>= 1) {
        if (t < s) red[t] += red[t + s];
        __syncthreads();
    }
    const float inv = 1.0f / red[0];

    v0.x *= inv; v0.y *= inv; v0.z *= inv; v0.w *= inv;
    v1.x *= inv; v1.y *= inv; v1.z *= inv; v1.w *= inv;
    ((float4*)p)[t] = v0;
    ((float4*)p)[t + 256] = v1;
}

// ----------------------------------------------------------------------------
extern "C" void kernel_launch(void* const* d_in, const int* in_sizes, int n_in,
                              void* d_out, int out_size)
{
    const float* x  = (const float*)d_in[0];
    const float* Wq = (const float*)d_in[1];
    const float* Wk = (const float*)d_in[2];
    const float* Wv = (const float*)d_in[3];
    const float* bq = (const float*)d_in[4];
    const float* bk = (const float*)d_in[5];
    const float* bv = (const float*)d_in[6];
    const float* Wo = (const float*)d_in[7];
    const float* bo = (const float*)d_in[8];
    float* out = (float*)d_out;

    float *pQ, *pK, *pV, *pS, *pC;
    cudaGetSymbolAddress((void**)&pQ, gQ);
    cudaGetSymbolAddress((void**)&pK, gK);
    cudaGetSymbolAddress((void**)&pV, gV);
    cudaGetSymbolAddress((void**)&pS, gS);
    cudaGetSymbolAddress((void**)&pC, gC);

    const float scale = 0.044194173824159216f;  // 1/sqrt(512)
    const dim3 blk(256);

    // QKV projections: per head, [4096,512] = x[4096,512] @ W[h][512,512] + b[h]
    mma_gemm<0, false><<<dim3(4, 32, Hh), blk>>>(x, Wq, pQ, bq, nullptr, Mrows, Dd, Dd, Dd, 1.0f);
    mma_gemm<0, false><<<dim3(4, 32, Hh), blk>>>(x, Wk, pK, bk, nullptr, Mrows, Dd, Dd, Dd, 1.0f);
    mma_gemm<0, false><<<dim3(4, 32, Hh), blk>>>(x, Wv, pV, bv, nullptr, Mrows, Dd, Dd, Dd, 1.0f);

    // scores = scale * Q @ K^T  per (b,h): [2048,2048]
    mma_gemm<1, true><<<dim3(16, 16, Bb * Hh), blk>>>(pQ, pK, pS, nullptr, nullptr, Ss, Ss, Dd, Ss, scale);

    // softmax over last axis
    softmax_kernel<<<Bb * Hh * Ss, 256>>>(pS);

    // O = P @ V per (b,h): [2048,512] -> written straight into concat layout gC[m][h*512+e]
    mma_gemm<2, false><<<dim3(4, 16, Bb * Hh), blk>>>(pS, pV, pC, nullptr, nullptr, Ss, Dd, Ss, CONCAT_K, 1.0f);

    // out = concat @ Wo + bo + x
    mma_gemm<3, false><<<dim3(4, 32, 1), blk>>>(pC, Wo, out, bo, x, Mrows, Dd, CONCAT_K, Dd, 1.0f);
}

// round 5
// speedup vs baseline: 5.8086x; 2.5273x over previous
#include <cuda_runtime.h>
#include <cuda_fp16.h>
#include <math.h>
#include <stdint.h>

// Problem constants
#define Bb 2
#define Hh 8
#define Ss 2048
#define Dd 512
#define Mrows (Bb * Ss)          // 4096
#define CONCAT_K (Hh * Dd)       // 4096

// ---------------------------------------------------------------------------
// Scratch (device globals; allocation is forbidden)
// ---------------------------------------------------------------------------
__device__ __half gx16[(size_t)Mrows * Dd];                 // 4 MB   [m][d]
__device__ __half gWqt16[(size_t)Hh * Dd * Dd];             // 4 MB   [h][e][d]
__device__ __half gWkt16[(size_t)Hh * Dd * Dd];
__device__ __half gWvt16[(size_t)Hh * Dd * Dd];
__device__ __half gWot16[(size_t)Dd * CONCAT_K];            // 4 MB   [e][hd]
__device__ __half gQ16[(size_t)Hh * Mrows * Dd];            // 32 MB  [h][m][e]
__device__ __half gK16[(size_t)Hh * Mrows * Dd];            // 32 MB
__device__ __half gV16[(size_t)Hh * Mrows * Dd];            // 32 MB  [h][m][e]
__device__ __half gVt16[(size_t)Hh * Dd * Mrows];           // 32 MB  [h][e][m]
__device__ float  gS[(size_t)Bb * Hh * Ss * Ss];            // 256 MB [z][q][k]
__device__ __half gP16[(size_t)Bb * Hh * Ss * Ss];          // 128 MB [z][q][k]
__device__ __half gC16[(size_t)Mrows * CONCAT_K];           // 32 MB  [m][h*D+e]

// ---------------------------------------------------------------------------
// helpers
// ---------------------------------------------------------------------------
__device__ __forceinline__ uint32_t smem_u32(const void* p) {
    uint32_t a;
    asm("{ .reg .u64 t; cvta.to.shared.u64 t, %1; cvt.u32.u64 %0, t; }" : "=r"(a) : "l"(p));
    return a;
}
#define CP16(dst, src) asm volatile("cp.async.cg.shared.global [%0], [%1], 16;" :: "r"(dst), "l"(src))
#define CP_COMMIT()    asm volatile("cp.async.commit_group;" ::: "memory")
#define CP_WAIT1()     asm volatile("cp.async.wait_group 1;" ::: "memory")

__device__ __forceinline__ uint32_t lds32(uint32_t a) {
    uint32_t v;
    asm volatile("ld.shared.b32 %0, [%1];" : "=r"(v) : "r"(a));
    return v;
}

__device__ __forceinline__ void mma16816(float* c, const uint32_t* a, const uint32_t* b) {
    asm volatile(
        "mma.sync.aligned.m16n8k16.row.col.f32.f16.f16.f32 "
        "{%0,%1,%2,%3},{%4,%5,%6,%7},{%8,%9},{%0,%1,%2,%3};\n"
        : "+f"(c[0]), "+f"(c[1]), "+f"(c[2]), "+f"(c[3])
        : "r"(a[0]), "r"(a[1]), "r"(a[2]), "r"(a[3]), "r"(b[0]), "r"(b[1]));
}

// ---------------------------------------------------------------------------
// fp16 GEMM: C = alpha * A @ B^T (+ bias) (+ resid)
// A: [M,K] fp16 K-major (lda halves), B: [N,K] fp16 K-major (ldb halves).
// CTA tile 128x128, K-chunk 32, 3-stage cp.async pipeline, 256 threads,
// 8 warps (2x4), warp tile 64x32, mma m16n8k16.
// Smem rows padded to 80B (40 halves): conflict-free for both STS (16B) and
// fragment LDS (bank = (20g + tig) mod 32, all 32 distinct).
//
// MODE: 0 = QKV proj (z=h, half out), 1 = QK^T (z=b*8+h, f32 out, alpha),
//       2 = P@V (z=b*8+h, half out into concat), 3 = out proj (f32 + bias + resid)
// ---------------------------------------------------------------------------
#define ROW_B 80u
#define A_ST_BYTES (128u * ROW_B)        // 10240
#define STAGE_BYTES (2u * A_ST_BYTES)    // 20480
#define HG_SMEM (3 * 20480)              // 61440

template <int MODE>
__global__ __launch_bounds__(256)
void hgemm(const __half* __restrict__ A0, const __half* __restrict__ B0,
           void* __restrict__ C0, const float* __restrict__ bias0,
           const float* __restrict__ resid0,
           int K, int lda, int ldb, int ldc, float alpha)
{
    extern __shared__ char sm[];
    const uint32_t sbase = smem_u32(sm);

    const int tid = threadIdx.x;
    const int lane = tid & 31;
    const int wid = tid >> 5;
    const int g = lane >> 2;
    const int tig = lane & 3;
    const int warp_m = wid >> 2;   // 0..1
    const int warp_n = wid & 3;    // 0..3
    const int bx = blockIdx.x, by = blockIdx.y;

    const __half* A = A0;
    const __half* B = B0;
    const float* bias = bias0;
    float* Cf = (float*)C0;
    __half* Ch = (__half*)C0;
    {
        const int z = blockIdx.z;
        if (MODE == 0) {
            B += (size_t)z * Dd * Dd;
            Ch += (size_t)z * Mrows * Dd;
            if (bias) bias += (size_t)z * Dd;
        } else if (MODE == 1) {
            const int h = z & 7, b = z >> 3;
            const size_t off = ((size_t)h * Mrows + (size_t)b * Ss) * Dd;
            A += off; B += off;
            Cf += (size_t)z * Ss * Ss;
        } else if (MODE == 2) {
            const int h = z & 7, b = z >> 3;
            A += (size_t)z * Ss * Ss;
            B += (size_t)h * Dd * Mrows + (size_t)b * Ss;
            Ch += (size_t)b * Ss * CONCAT_K + (size_t)h * Dd;
        }
    }

    const __half* Arow = A + (size_t)(by * 128) * lda;
    const __half* Brow = B + (size_t)(bx * 128) * ldb;

    const int r0l = tid >> 2, r1l = (tid + 256) >> 2;   // load rows for the 2 iters
    const int f0l = tid & 3,  f1l = (tid + 256) & 3;

    auto issue = [&](int c, int st) {
        const __half* Ac = Arow + c * 32;
        const __half* Bc = Brow + c * 32;
        const uint32_t sA = sbase + (uint32_t)st * STAGE_BYTES;
        const uint32_t sB = sA + A_ST_BYTES;
        CP16(sA + (uint32_t)r0l * ROW_B + f0l * 16, Ac + (size_t)r0l * lda + f0l * 8);
        CP16(sB + (uint32_t)r0l * ROW_B + f0l * 16, Bc + (size_t)r0l * ldb + f0l * 8);
        CP16(sA + (uint32_t)r1l * ROW_B + f1l * 16, Ac + (size_t)r1l * lda + f1l * 8);
        CP16(sB + (uint32_t)r1l * ROW_B + f1l * 16, Bc + (size_t)r1l * ldb + f1l * 8);
    };

    float acc[4][4][4];
#pragma unroll
    for (int mi = 0; mi < 4; mi++)
#pragma unroll
        for (int ni = 0; ni < 4; ni++)
#pragma unroll
            for (int r = 0; r < 4; r++) acc[mi][ni][r] = 0.0f;

    const int nchunks = K >> 5;

    issue(0, 0); CP_COMMIT();
    issue(1, 1); CP_COMMIT();

    for (int c = 0; c < nchunks; c++) {
        CP_WAIT1();
        __syncthreads();

        const int st = c % 3;
        const uint32_t baseA = sbase + (uint32_t)st * STAGE_BYTES;
        const uint32_t baseB = baseA + A_ST_BYTES;
#pragma unroll
        for (int ks = 0; ks < 2; ks++) {
            const uint32_t kb = (uint32_t)(ks * 8 + tig) * 4;   // byte offset in row
            uint32_t a[4][4], b[4][2];
#pragma unroll
            for (int mi = 0; mi < 4; mi++) {
                const uint32_t ra = baseA + (uint32_t)(warp_m * 64 + mi * 16 + g) * ROW_B + kb;
                a[mi][0] = lds32(ra);
                a[mi][1] = lds32(ra + 8 * ROW_B);
                a[mi][2] = lds32(ra + 16);
                a[mi][3] = lds32(ra + 8 * ROW_B + 16);
            }
#pragma unroll
            for (int ni = 0; ni < 4; ni++) {
                const uint32_t rb = baseB + (uint32_t)(warp_n * 32 + ni * 8 + g) * ROW_B + kb;
                b[ni][0] = lds32(rb);
                b[ni][1] = lds32(rb + 16);
            }
#pragma unroll
            for (int mi = 0; mi < 4; mi++)
#pragma unroll
                for (int ni = 0; ni < 4; ni++)
                    mma16816(acc[mi][ni], a[mi], b[ni]);
        }

        if (c + 2 < nchunks) issue(c + 2, (c + 2) % 3);
        CP_COMMIT();
    }

    // epilogue
#pragma unroll
    for (int mi = 0; mi < 4; mi++) {
        const int row0 = by * 128 + warp_m * 64 + mi * 16 + g;
#pragma unroll
        for (int ni = 0; ni < 4; ni++) {
            const int col = bx * 128 + warp_n * 32 + ni * 8 + 2 * tig;
            float2 v0, v1;
            v0.x = acc[mi][ni][0] * alpha; v0.y = acc[mi][ni][1] * alpha;
            v1.x = acc[mi][ni][2] * alpha; v1.y = acc[mi][ni][3] * alpha;
            if (MODE == 0 || MODE == 3) {
                const float b0 = bias[col], b1 = bias[col + 1];
                v0.x += b0; v0.y += b1;
                v1.x += b0; v1.y += b1;
            }
            if (MODE == 3) {
                const float2 r0 = *(const float2*)&resid0[(size_t)row0 * ldc + col];
                const float2 r1 = *(const float2*)&resid0[(size_t)(row0 + 8) * ldc + col];
                v0.x += r0.x; v0.y += r0.y;
                v1.x += r1.x; v1.y += r1.y;
            }
            if (MODE == 0 || MODE == 2) {
                *(__half2*)&Ch[(size_t)row0 * ldc + col] = __floats2half2_rn(v0.x, v0.y);
                *(__half2*)&Ch[(size_t)(row0 + 8) * ldc + col] = __floats2half2_rn(v1.x, v1.y);
            } else {
                *(float2*)&Cf[(size_t)row0 * ldc + col] = v0;
                *(float2*)&Cf[(size_t)(row0 + 8) * ldc + col] = v1;
            }
        }
    }
}

// ---------------------------------------------------------------------------
// fp32 -> fp16 elementwise (float4 granularity)
// ---------------------------------------------------------------------------
__global__ __launch_bounds__(256)
void cvt_half(const float* __restrict__ in, __half* __restrict__ out)
{
    const size_t i = (size_t)blockIdx.x * 256 + threadIdx.x;
    const float4 v = ((const float4*)in)[i];
    ((__half2*)out)[2 * i]     = __floats2half2_rn(v.x, v.y);
    ((__half2*)out)[2 * i + 1] = __floats2half2_rn(v.z, v.w);
}

// ---------------------------------------------------------------------------
// fp32 [z][R][C] -> fp16 transposed [z][C][R]
// ---------------------------------------------------------------------------
__global__ __launch_bounds__(256)
void cvtT(const float* __restrict__ in, __half* __restrict__ out, int R, int C)
{
    __shared__ float t[32][33];
    in  += (size_t)blockIdx.z * R * C;
    out += (size_t)blockIdx.z * R * C;
    const int c0 = blockIdx.x * 32, r0 = blockIdx.y * 32;
    const int tx = threadIdx.x & 31, ty = threadIdx.x >> 5;
#pragma unroll
    for (int i = 0; i < 32; i += 8)
        t[ty + i][tx] = in[(size_t)(r0 + ty + i) * C + c0 + tx];
    __syncthreads();
#pragma unroll
    for (int i = 0; i < 32; i += 8)
        out[(size_t)(c0 + ty + i) * R + r0 + tx] = __float2half(t[tx][ty + i]);
}

// ---------------------------------------------------------------------------
// fp16 [z][R][C] -> fp16 transposed [z][C][R]
// ---------------------------------------------------------------------------
__global__ __launch_bounds__(256)
void transpose16(const __half* __restrict__ in, __half* __restrict__ out, int R, int C)
{
    __shared__ __half t[32][34];
    in  += (size_t)blockIdx.z * R * C;
    out += (size_t)blockIdx.z * R * C;
    const int c0 = blockIdx.x * 32, r0 = blockIdx.y * 32;
    const int tx = threadIdx.x & 31, ty = threadIdx.x >> 5;
#pragma unroll
    for (int i = 0; i < 32; i += 8)
        t[ty + i][tx] = in[(size_t)(r0 + ty + i) * C + c0 + tx];
    __syncthreads();
#pragma unroll
    for (int i = 0; i < 32; i += 8)
        out[(size_t)(c0 + ty + i) * R + r0 + tx] = t[tx][ty + i];
}

// ---------------------------------------------------------------------------
// Row softmax fp32 in -> fp16 out
// ---------------------------------------------------------------------------
__global__ __launch_bounds__(256)
void softmax_kernel(const float* __restrict__ S, __half* __restrict__ P)
{
    __shared__ float red[256];
    const float* p = S + (size_t)blockIdx.x * Ss;
    __half* q = P + (size_t)blockIdx.x * Ss;
    const int t = threadIdx.x;

    float4 v0 = ((const float4*)p)[t];
    float4 v1 = ((const float4*)p)[t + 256];

    float m = fmaxf(fmaxf(fmaxf(v0.x, v0.y), fmaxf(v0.z, v0.w)),
                    fmaxf(fmaxf(v1.x, v1.y), fmaxf(v1.z, v1.w)));
    red[t] = m;
    __syncthreads();
    for (int s = 128; s > 0; s >>= 1) {
        if (t < s) red[t] = fmaxf(red[t], red[t + s]);
        __syncthreads();
    }
    m = red[0];
    __syncthreads();

    v0.x = expf(v0.x - m); v0.y = expf(v0.y - m);
    v0.z = expf(v0.z - m); v0.w = expf(v0.w - m);
    v1.x = expf(v1.x - m); v1.y = expf(v1.y - m);
    v1.z = expf(v1.z - m); v1.w = expf(v1.w - m);

    red[t] = v0.x + v0.y + v0.z + v0.w + v1.x + v1.y + v1.z + v1.w;
    __syncthreads();
    for (int s = 128; s > 0; s >>= 1) {
        if (t < s) red[t] += red[t + s];
        __syncthreads();
    }
    const float inv = 1.0f / red[0];

    ((__half2*)q)[2 * t]           = __floats2half2_rn(v0.x * inv, v0.y * inv);
    ((__half2*)q)[2 * t + 1]       = __floats2half2_rn(v0.z * inv, v0.w * inv);
    ((__half2*)q)[512 + 2 * t]     = __floats2half2_rn(v1.x * inv, v1.y * inv);
    ((__half2*)q)[512 + 2 * t + 1] = __floats2half2_rn(v1.z * inv, v1.w * inv);
}

// ---------------------------------------------------------------------------
extern "C" void kernel_launch(void* const* d_in, const int* in_sizes, int n_in,
                              void* d_out, int out_size)
{
    const float* x  = (const float*)d_in[0];
    const float* Wq = (const float*)d_in[1];
    const float* Wk = (const float*)d_in[2];
    const float* Wv = (const float*)d_in[3];
    const float* bq = (const float*)d_in[4];
    const float* bk = (const float*)d_in[5];
    const float* bv = (const float*)d_in[6];
    const float* Wo = (const float*)d_in[7];
    const float* bo = (const float*)d_in[8];
    float* out = (float*)d_out;

    __half *px16, *pWqt, *pWkt, *pWvt, *pWot, *pQ, *pK, *pV, *pVt, *pP, *pC;
    float *pS;
    cudaGetSymbolAddress((void**)&px16, gx16);
    cudaGetSymbolAddress((void**)&pWqt, gWqt16);
    cudaGetSymbolAddress((void**)&pWkt, gWkt16);
    cudaGetSymbolAddress((void**)&pWvt, gWvt16);
    cudaGetSymbolAddress((void**)&pWot, gWot16);
    cudaGetSymbolAddress((void**)&pQ, gQ16);
    cudaGetSymbolAddress((void**)&pK, gK16);
    cudaGetSymbolAddress((void**)&pV, gV16);
    cudaGetSymbolAddress((void**)&pVt, gVt16);
    cudaGetSymbolAddress((void**)&pS, gS);
    cudaGetSymbolAddress((void**)&pP, gP16);
    cudaGetSymbolAddress((void**)&pC, gC16);

    cudaFuncSetAttribute((const void*)hgemm<0>, cudaFuncAttributeMaxDynamicSharedMemorySize, HG_SMEM);
    cudaFuncSetAttribute((const void*)hgemm<1>, cudaFuncAttributeMaxDynamicSharedMemorySize, HG_SMEM);
    cudaFuncSetAttribute((const void*)hgemm<2>, cudaFuncAttributeMaxDynamicSharedMemorySize, HG_SMEM);
    cudaFuncSetAttribute((const void*)hgemm<3>, cudaFuncAttributeMaxDynamicSharedMemorySize, HG_SMEM);

    const float scale = 0.044194173824159216f;  // 1/sqrt(512)
    const dim3 blk(256);

    // 0) convert inputs to fp16 K-major operands
    cvt_half<<<Mrows * Dd / 1024, blk>>>(x, px16);
    cvtT<<<dim3(16, 16, Hh), blk>>>(Wq, pWqt, Dd, Dd);
    cvtT<<<dim3(16, 16, Hh), blk>>>(Wk, pWkt, Dd, Dd);
    cvtT<<<dim3(16, 16, Hh), blk>>>(Wv, pWvt, Dd, Dd);
    cvtT<<<dim3(16, 128, 1), blk>>>(Wo, pWot, CONCAT_K, Dd);

    // 1) QKV projections: [4096,512] = x16 @ Wt16(h)^T, fp16 outputs
    hgemm<0><<<dim3(4, 32, Hh), blk, HG_SMEM>>>(px16, pWqt, pQ, bq, nullptr, Dd, Dd, Dd, Dd, 1.0f);
    hgemm<0><<<dim3(4, 32, Hh), blk, HG_SMEM>>>(px16, pWkt, pK, bk, nullptr, Dd, Dd, Dd, Dd, 1.0f);
    hgemm<0><<<dim3(4, 32, Hh), blk, HG_SMEM>>>(px16, pWvt, pV, bv, nullptr, Dd, Dd, Dd, Dd, 1.0f);

    // 1b) V -> transposed [h][e][m]
    transpose16<<<dim3(16, 128, Hh), blk>>>(pV, pVt, Mrows, Dd);

    // 2) scores = scale * Q @ K^T, fp32 out
    hgemm<1><<<dim3(16, 16, Bb * Hh), blk, HG_SMEM>>>(pQ, pK, pS, nullptr, nullptr, Dd, Dd, Dd, Ss, scale);

    // 3) softmax -> fp16 P
    softmax_kernel<<<Bb * Hh * Ss, 256>>>(pS, pP);

    // 4) O = P @ V -> fp16 concat layout [m][h*512+e]
    hgemm<2><<<dim3(4, 16, Bb * Hh), blk, HG_SMEM>>>(pP, pVt, pC, nullptr, nullptr, Ss, Ss, Mrows, CONCAT_K, 1.0f);

    // 5) out = concat @ Wo^T + bo + x, fp32
    hgemm<3><<<dim3(4, 32, 1), blk, HG_SMEM>>>(pC, pWot, out, bo, x, CONCAT_K, CONCAT_K, CONCAT_K, Dd, 1.0f);
}